// round 10
// baseline (speedup 1.0000x reference)
#include <cuda_runtime.h>
#include <cstddef>

// GATNE-T fused, warp-per-batch-element, zero CTA barriers (R10).
// R9 + fully interleaved attention phase (4 t-chains pipelined: dots,
// tanh, and shfl butterflies all 4-way ILP).
//
// Inputs (metadata order):
//  0 targets   int32  [B]
//  1 types     int32  [B]
//  2 neighbors int32  [B,T,S]
//  3 base_node_embeddings float [V,E]
//  4 node_type_embeddings float [V,T,D]
//  5 trans_weights    float [T,D,E]
//  6 trans_weights_s1 float [T,D,A]
//  7 trans_weights_s2 float [T,A,1]
// Output: float [B,E]

namespace {
constexpr int T = 4;
constexpr int S = 10;
constexpr int D = 32;
constexpr int E = 128;
constexpr int A = 32;
constexpr int NW = 8;          // warps per CTA
}

__device__ __forceinline__ float tanh_approx(float x) {
    float y;
    asm("tanh.approx.f32 %0, %1;" : "=f"(y) : "f"(x));
    return y;
}

__global__ __launch_bounds__(32 * NW) void gatne_warp(
    const int*   __restrict__ targets,
    const int*   __restrict__ types,
    const int*   __restrict__ neighbors,  // [B,T,S]
    const float* __restrict__ base_emb,   // [V,E]
    const float* __restrict__ nte,        // [V,T,D]
    const float* __restrict__ tw,         // [T,D,E]
    const float* __restrict__ tw1,        // [T,D,A]
    const float* __restrict__ tw2,        // [T,A]
    float*       __restrict__ out,        // [B,E]
    int B)
{
    const int wid  = threadIdx.x >> 5;
    const int lane = threadIdx.x & 31;

    // per-warp scratch (no cross-warp sharing, no CTA barriers)
    __shared__ float sh_agg[NW][T][D];
    __shared__ float sh_nat[NW][D];

    const int b = blockIdx.x * NW + wid;
    if (b >= B) return;

    const int ty  = types[b];      // broadcast LDG
    const int tgt = targets[b];    // broadcast LDG

    // PREFETCH random base_emb gather: overlaps the neighbor gathers.
    const float4 bv = __ldg((const float4*)(base_emb + (size_t)tgt * E) + lane);

    // neighbor indices: 2 coalesced loads for 40 ints
    const int* nbp = neighbors + (size_t)b * (T * S);
    const int nbv0 = nbp[lane];
    const int nbv1 = (lane < T * S - 32) ? nbp[32 + lane] : 0;

    // gather + mean: 40 independent coalesced 128B loads, lane = d
    float acc[T];
    #pragma unroll
    for (int t = 0; t < T; ++t) acc[t] = 0.0f;

    #pragma unroll
    for (int t = 0; t < T; ++t) {
        #pragma unroll
        for (int s = 0; s < S; ++s) {
            const int flat = t * S + s;
            const int v = (flat < 32)
                ? __shfl_sync(0xffffffffu, nbv0, flat)
                : __shfl_sync(0xffffffffu, nbv1, flat - 32);
            acc[t] += __ldg(&nte[(size_t)v * (T * D) + t * D + lane]);
        }
    }

    // attention weights (L1-resident), loads fly while gathers complete
    float w1col[D];                        // W1[ty][d][lane], lane = a
    {
        const float* w1 = tw1 + (size_t)ty * (D * A);
        #pragma unroll
        for (int d = 0; d < D; ++d) w1col[d] = __ldg(&w1[d * A + lane]);
    }
    const float tw2v = __ldg(&tw2[ty * A + lane]);

    #pragma unroll
    for (int t = 0; t < T; ++t) {
        acc[t] *= (1.0f / (float)S);       // agg[t][lane]
        sh_agg[wid][t][lane] = acc[t];
    }
    __syncwarp();

    // ---- attention: ALL FOUR t-chains interleaved ----
    // dots
    float dt[T];
    {
        float c0[T], c1[T];
        #pragma unroll
        for (int t = 0; t < T; ++t) { c0[t] = 0.0f; c1[t] = 0.0f; }
        const float4* ap0 = (const float4*)sh_agg[wid][0];
        const float4* ap1 = (const float4*)sh_agg[wid][1];
        const float4* ap2 = (const float4*)sh_agg[wid][2];
        const float4* ap3 = (const float4*)sh_agg[wid][3];
        #pragma unroll
        for (int q = 0; q < D / 4; ++q) {
            const float4 v0 = ap0[q];      // 4 independent LDS.128 broadcasts
            const float4 v1 = ap1[q];
            const float4 v2 = ap2[q];
            const float4 v3 = ap3[q];
            const float wa = w1col[4 * q + 0], wb = w1col[4 * q + 1];
            const float wc = w1col[4 * q + 2], wd = w1col[4 * q + 3];
            c0[0] = fmaf(v0.x, wa, c0[0]); c1[0] = fmaf(v0.y, wb, c1[0]);
            c0[0] = fmaf(v0.z, wc, c0[0]); c1[0] = fmaf(v0.w, wd, c1[0]);
            c0[1] = fmaf(v1.x, wa, c0[1]); c1[1] = fmaf(v1.y, wb, c1[1]);
            c0[1] = fmaf(v1.z, wc, c0[1]); c1[1] = fmaf(v1.w, wd, c1[1]);
            c0[2] = fmaf(v2.x, wa, c0[2]); c1[2] = fmaf(v2.y, wb, c1[2]);
            c0[2] = fmaf(v2.z, wc, c0[2]); c1[2] = fmaf(v2.w, wd, c1[2]);
            c0[3] = fmaf(v3.x, wa, c0[3]); c1[3] = fmaf(v3.y, wb, c1[3]);
            c0[3] = fmaf(v3.z, wc, c0[3]); c1[3] = fmaf(v3.w, wd, c1[3]);
        }
        #pragma unroll
        for (int t = 0; t < T; ++t) dt[t] = c0[t] + c1[t];
    }

    // tanh (4 independent MUFU) + weighted u
    float u0 = tanh_approx(dt[0]) * tw2v;
    float u1 = tanh_approx(dt[1]) * tw2v;
    float u2 = tanh_approx(dt[2]) * tw2v;
    float u3 = tanh_approx(dt[3]) * tw2v;

    // interleaved butterflies: 4 independent 5-deep chains
    #pragma unroll
    for (int off = 16; off > 0; off >>= 1) {
        u0 += __shfl_xor_sync(0xffffffffu, u0, off);
        u1 += __shfl_xor_sync(0xffffffffu, u1, off);
        u2 += __shfl_xor_sync(0xffffffffu, u2, off);
        u3 += __shfl_xor_sync(0xffffffffu, u3, off);
    }

    // softmax over T=4 + attended embedding (lane = d)
    const float m  = fmaxf(fmaxf(u0, u1), fmaxf(u2, u3));
    const float e0 = __expf(u0 - m), e1 = __expf(u1 - m);
    const float e2 = __expf(u2 - m), e3 = __expf(u3 - m);
    const float inv = 1.0f / (e0 + e1 + e2 + e3);
    sh_nat[wid][lane] = (e0 * acc[0] + e1 * acc[1] +
                         e2 * acc[2] + e3 * acc[3]) * inv;
    __syncwarp();

    // projection: lane owns e in [4*lane, 4*lane+4); 32 LDG.128 L1 hits
    const float* wbase = tw + (size_t)ty * (D * E) + 4 * lane;
    float4 a4 = make_float4(0.f, 0.f, 0.f, 0.f);
    float4 b4 = make_float4(0.f, 0.f, 0.f, 0.f);
    const float4* np = (const float4*)sh_nat[wid];
    #pragma unroll
    for (int q = 0; q < D / 4; ++q) {
        const float4 n4 = np[q];           // broadcast LDS.128
        const float4 w0 = __ldg((const float4*)(wbase + (4 * q + 0) * E));
        const float4 w1 = __ldg((const float4*)(wbase + (4 * q + 1) * E));
        const float4 w2 = __ldg((const float4*)(wbase + (4 * q + 2) * E));
        const float4 w3 = __ldg((const float4*)(wbase + (4 * q + 3) * E));
        a4.x = fmaf(n4.x, w0.x, a4.x); a4.y = fmaf(n4.x, w0.y, a4.y);
        a4.z = fmaf(n4.x, w0.z, a4.z); a4.w = fmaf(n4.x, w0.w, a4.w);
        b4.x = fmaf(n4.y, w1.x, b4.x); b4.y = fmaf(n4.y, w1.y, b4.y);
        b4.z = fmaf(n4.y, w1.z, b4.z); b4.w = fmaf(n4.y, w1.w, b4.w);
        a4.x = fmaf(n4.z, w2.x, a4.x); a4.y = fmaf(n4.z, w2.y, a4.y);
        a4.z = fmaf(n4.z, w2.z, a4.z); a4.w = fmaf(n4.z, w2.w, a4.w);
        b4.x = fmaf(n4.w, w3.x, b4.x); b4.y = fmaf(n4.w, w3.y, b4.y);
        b4.z = fmaf(n4.w, w3.z, b4.z); b4.w = fmaf(n4.w, w3.w, b4.w);
    }

    const float4 val = make_float4(a4.x + b4.x + bv.x, a4.y + b4.y + bv.y,
                                   a4.z + b4.z + bv.z, a4.w + b4.w + bv.w);

    // l2 norm: warp butterfly = exact sum over all 128 outputs
    float ss = val.x * val.x + val.y * val.y + val.z * val.z + val.w * val.w;
    #pragma unroll
    for (int off = 16; off > 0; off >>= 1)
        ss += __shfl_xor_sync(0xffffffffu, ss, off);
    const float r = rsqrtf(fmaxf(ss, 1e-12f));

    const float4 o = make_float4(val.x * r, val.y * r, val.z * r, val.w * r);
    ((float4*)(out + (size_t)b * E))[lane] = o;
}

extern "C" void kernel_launch(void* const* d_in, const int* in_sizes, int n_in,
                              void* d_out, int out_size) {
    const int*   targets   = (const int*)  d_in[0];
    const int*   types     = (const int*)  d_in[1];
    const int*   neighbors = (const int*)  d_in[2];
    const float* base_emb  = (const float*)d_in[3];
    const float* nte       = (const float*)d_in[4];
    const float* tw        = (const float*)d_in[5];
    const float* tw1       = (const float*)d_in[6];
    const float* tw2       = (const float*)d_in[7];
    float* out = (float*)d_out;

    const int B = in_sizes[0];
    const int grid = (B + NW - 1) / NW;
    gatne_warp<<<grid, 32 * NW>>>(targets, types, neighbors,
                                  base_emb, nte, tw, tw1, tw2, out, B);
}